// round 4
// baseline (speedup 1.0000x reference)
#include <cuda_runtime.h>
#include <cstddef>

// ---------------------------------------------------------------------------
// WindowAttention: x[4096,49,256] -> qkv -> per-window attention -> proj
//   B=4096 windows, N=49 tokens, C=256, H=8 heads, hd=32
// fp32 baseline w/ Round-1 bias-table fix + double-buffered SGEMM.
// tcgen05 upgrade of K1/K3 gated on first measured pass (rel_err headroom).
// ---------------------------------------------------------------------------

#define BATCH   4096
#define NTOK    49
#define HEADS   8
#define DIM     256
#define HD      32
#define QKVDIM  768           // 3 * DIM, layout per row: [s(3)][h(8)][d(32)]
#define MROWS   (BATCH * NTOK)  // 200704

// Scratch (static __device__ arrays: allocation-guard-safe)
__device__ float g_qkv[(size_t)BATCH * NTOK * QKVDIM];   // ~616 MB
__device__ float g_att[(size_t)BATCH * NTOK * DIM];      // ~205 MB

// ---------------------------------------------------------------------------
// SGEMM: C[M,N] = A[M,K] @ B[K,N] + bias[N]
// BM=128, BN=128, BK=8, TM=TN=8, 256 threads, ping-pong smem double buffer.
// Requires M%128==0, N%128==0, K%8==0.
// ---------------------------------------------------------------------------
template <int BM, int BN, int BK, int TM, int TN>
__global__ __launch_bounds__(256) void sgemm_bias_kernel(
    const float* __restrict__ A, const float* __restrict__ B,
    const float* __restrict__ bias, float* __restrict__ C,
    int M, int N, int K)
{
    __shared__ float As[2][BK][BM];   // A stored transposed: As[buf][k][m]
    __shared__ float Bs[2][BK][BN];   // Bs[buf][k][n]

    const int tid  = threadIdx.x;
    const int row0 = blockIdx.y * BM;
    const int col0 = blockIdx.x * BN;

    // A tile load map: BM*BK/4 = 256 float4, one per thread
    const int aRow = tid / (BK / 4);          // 0..127
    const int aCol = (tid % (BK / 4)) * 4;    // 0 or 4
    // B tile load map: BK*BN/4 = 256 float4, one per thread
    const int bRow = tid / (BN / 4);          // 0..7
    const int bCol = (tid % (BN / 4)) * 4;    // 0..124

    const int tRow = (tid / (BN / TN)) * TM;  // 0..120
    const int tCol = (tid % (BN / TN)) * TN;  // 0..120

    float acc[TM][TN];
    #pragma unroll
    for (int i = 0; i < TM; i++)
        #pragma unroll
        for (int j = 0; j < TN; j++) acc[i][j] = 0.f;

    float regM[TM], regN[TN];

    const float* Ab = A + (size_t)row0 * K;
    const float* Bb = B + col0;

    // Prologue: stage tile 0 into buffer 0
    {
        float4 a4 = *(const float4*)(Ab + (size_t)aRow * K + aCol);
        As[0][aCol + 0][aRow] = a4.x;
        As[0][aCol + 1][aRow] = a4.y;
        As[0][aCol + 2][aRow] = a4.z;
        As[0][aCol + 3][aRow] = a4.w;
        float4 b4 = *(const float4*)(Bb + (size_t)bRow * N + bCol);
        *(float4*)(&Bs[0][bRow][bCol]) = b4;
    }
    __syncthreads();

    const int NT = K / BK;
    int buf = 0;

    for (int t = 0; t < NT; t++) {
        // Prefetch next tile from GMEM into registers (overlaps with compute)
        float4 a4n, b4n;
        const bool more = (t + 1 < NT);
        if (more) {
            const int k0 = (t + 1) * BK;
            a4n = *(const float4*)(Ab + (size_t)aRow * K + (k0 + aCol));
            b4n = *(const float4*)(Bb + (size_t)(k0 + bRow) * N + bCol);
        }

        // Compute on current buffer
        #pragma unroll
        for (int k = 0; k < BK; k++) {
            #pragma unroll
            for (int i = 0; i < TM; i += 4)
                *(float4*)(&regM[i]) = *(const float4*)(&As[buf][k][tRow + i]);
            #pragma unroll
            for (int j = 0; j < TN; j += 4)
                *(float4*)(&regN[j]) = *(const float4*)(&Bs[buf][k][tCol + j]);
            #pragma unroll
            for (int i = 0; i < TM; i++)
                #pragma unroll
                for (int j = 0; j < TN; j++)
                    acc[i][j] += regM[i] * regN[j];
        }

        // Drain prefetch into the alternate buffer; single barrier per iter
        if (more) {
            const int nb = buf ^ 1;
            As[nb][aCol + 0][aRow] = a4n.x;
            As[nb][aCol + 1][aRow] = a4n.y;
            As[nb][aCol + 2][aRow] = a4n.z;
            As[nb][aCol + 3][aRow] = a4n.w;
            *(float4*)(&Bs[nb][bRow][bCol]) = b4n;
            __syncthreads();
            buf = nb;
        }
    }

    // Epilogue: add bias, vectorized stores
    float bv[TN];
    #pragma unroll
    for (int j = 0; j < TN; j++) bv[j] = bias[col0 + tCol + j];

    #pragma unroll
    for (int i = 0; i < TM; i++) {
        float* Crow = C + (size_t)(row0 + tRow + i) * N + (col0 + tCol);
        #pragma unroll
        for (int j = 0; j < TN; j += 4) {
            float4 o;
            o.x = acc[i][j + 0] + bv[j + 0];
            o.y = acc[i][j + 1] + bv[j + 1];
            o.z = acc[i][j + 2] + bv[j + 2];
            o.w = acc[i][j + 3] + bv[j + 3];
            *(float4*)(Crow + j) = o;
        }
    }
}

// ---------------------------------------------------------------------------
// Fused attention: one block per (head, window). 128 threads (4 warps).
// Each warp owns rows i = w, w+4, ... Per row: scores (dot over hd=32),
// +rel-pos bias, softmax via warp shuffles, AV with V cached in registers.
// ---------------------------------------------------------------------------
__global__ __launch_bounds__(128) void attn_kernel(
    const float* __restrict__ qkv, const float* __restrict__ bias_table,
    float* __restrict__ out)
{
    const int h    = blockIdx.x;
    const int b    = blockIdx.y;
    const int t    = threadIdx.x;
    const int w    = t >> 5;
    const int lane = t & 31;

    // padded stride 33: bank for [row*33 + d] = (row + d) & 31 -> conflict-free
    __shared__ float sq[NTOK * 33];
    __shared__ float sk[64 * 33];       // rows 49..63 zero (for j = lane+32 path)
    __shared__ float sv[NTOK * 33];
    __shared__ float sbt[169];          // bias_table[:, h]

    // zero pad rows of K
    for (int idx = t; idx < (64 - NTOK) * 33; idx += 128) sk[NTOK * 33 + idx] = 0.f;
    // 169 entries, 128 threads -> strided loop (Round-1 bug: `if (t<169)` left
    // sbt[128..168] uninitialized -> 0.102 rel_err)
    for (int idx = t; idx < 169; idx += 128) sbt[idx] = bias_table[idx * HEADS + h];

    const float scale = 0.17677669529663687f;  // 1/sqrt(32)
    const float* base = qkv + (size_t)b * NTOK * QKVDIM + (size_t)h * HD;
    for (int idx = t; idx < NTOK * HD; idx += 128) {
        const int n = idx >> 5, d = idx & 31;
        const float* p = base + (size_t)n * QKVDIM + d;
        sq[n * 33 + d] = p[0] * scale;       // q
        sk[n * 33 + d] = p[DIM];             // k
        sv[n * 33 + d] = p[2 * DIM];         // v
    }
    __syncthreads();

    // V cached in registers: lane holds v[j][lane] for all j
    float vreg[NTOK];
    #pragma unroll
    for (int j = 0; j < NTOK; j++) vreg[j] = sv[j * 33 + lane];

    const int  j0  = lane;
    const int  j1  = lane + 32;
    const bool v1  = (j1 < NTOK);
    const int  hj0 = j0 / 7, wj0 = j0 % 7;
    const int  j1c = v1 ? j1 : 0;
    const int  hj1 = j1c / 7, wj1 = j1c % 7;

    float* outb = out + (size_t)b * NTOK * DIM + (size_t)h * HD + lane;

    for (int i = w; i < NTOK; i += 4) {
        const int hi = i / 7, wi = i % 7;
        const float* qrow  = sq + i * 33;
        const float* krow0 = sk + j0 * 33;
        const float* krow1 = sk + j1 * 33;    // padded-zero rows if j1 >= 49

        float a0 = 0.f, a1 = 0.f;
        #pragma unroll
        for (int d = 0; d < HD; d++) {
            const float qv = qrow[d];
            a0 += qv * krow0[d];
            a1 += qv * krow1[d];
        }
        a0 += sbt[(hi - hj0 + 6) * 13 + (wi - wj0 + 6)];
        a1 = v1 ? (a1 + sbt[(hi - hj1 + 6) * 13 + (wi - wj1 + 6)]) : -3.0e38f;

        // row softmax over 49 keys (lane j0 holds one, lanes<17 also j1)
        float m = fmaxf(a0, a1);
        #pragma unroll
        for (int o = 16; o > 0; o >>= 1)
            m = fmaxf(m, __shfl_xor_sync(0xffffffffu, m, o));
        float p0 = __expf(a0 - m);
        float p1 = v1 ? __expf(a1 - m) : 0.f;
        float s = p0 + p1;
        #pragma unroll
        for (int o = 16; o > 0; o >>= 1)
            s += __shfl_xor_sync(0xffffffffu, s, o);
        const float r = 1.f / s;
        p0 *= r;
        p1 *= r;

        // AV: out[i][lane] = sum_j p[j] * v[j][lane]; p broadcast via shfl
        float o = 0.f;
        #pragma unroll
        for (int j = 0; j < 32; j++)
            o += __shfl_sync(0xffffffffu, p0, j) * vreg[j];
        #pragma unroll
        for (int j = 0; j < 17; j++)
            o += __shfl_sync(0xffffffffu, p1, j) * vreg[32 + j];

        outb[(size_t)i * DIM] = o;   // layout [b, n, h, d]
    }
}

// ---------------------------------------------------------------------------
extern "C" void kernel_launch(void* const* d_in, const int* in_sizes, int n_in,
                              void* d_out, int out_size)
{
    const float* x          = (const float*)d_in[0];
    const float* w_qkv      = (const float*)d_in[1];
    const float* b_qkv      = (const float*)d_in[2];
    const float* w_proj     = (const float*)d_in[3];
    const float* b_proj     = (const float*)d_in[4];
    const float* bias_table = (const float*)d_in[5];
    float* out = (float*)d_out;

    float* qkvp = nullptr;
    float* attp = nullptr;
    cudaGetSymbolAddress((void**)&qkvp, g_qkv);
    cudaGetSymbolAddress((void**)&attp, g_att);

    // K1: qkv = x @ w_qkv + b_qkv   [200704,256]x[256,768]
    {
        dim3 grid(QKVDIM / 128, MROWS / 128);
        sgemm_bias_kernel<128, 128, 8, 8, 8><<<grid, 256>>>(
            x, w_qkv, b_qkv, qkvp, MROWS, QKVDIM, DIM);
    }

    // K2: fused window attention -> g_att  [b, n, h, d]
    {
        dim3 grid(HEADS, BATCH);
        attn_kernel<<<grid, 128>>>(qkvp, bias_table, attp);
    }

    // K3: out = g_att @ w_proj + b_proj   [200704,256]x[256,256]
    {
        dim3 grid(DIM / 128, MROWS / 128);
        sgemm_bias_kernel<128, 128, 8, 8, 8><<<grid, 256>>>(
            attp, w_proj, b_proj, out, MROWS, DIM, DIM);
    }
}

// round 6
// speedup vs baseline: 1.4492x; 1.4492x over previous
#include <cuda_runtime.h>
#include <cuda_bf16.h>
#include <cstdint>
#include <cstddef>

// ---------------------------------------------------------------------------
// WindowAttention: base-PTX tensor-core path (harness compiles compute_103,
// so NO tcgen05/'a'-features -- use mma.sync bf16 + ldmatrix + cp.async).
// K1/K3: D = Ahi@Bhi^T + Ahi@Blo^T + Alo@Bhi^T  (3-term bf16 split, fp32 acc)
// ---------------------------------------------------------------------------

#define BATCH   4096
#define NTOK    49
#define HEADS   8
#define DIM     256
#define HD      32
#define QKVDIM  768
#define MROWS   (BATCH * NTOK)   // 200704 = 1568 * 128
#define KDIM    256

// ---- scratch (static __device__: allocation-guard-safe) -------------------
__device__ float         g_qkv[(size_t)MROWS * QKVDIM];
__device__ __nv_bfloat16 g_xhi[(size_t)MROWS * DIM];
__device__ __nv_bfloat16 g_xlo[(size_t)MROWS * DIM];
__device__ __nv_bfloat16 g_ahi[(size_t)MROWS * DIM];
__device__ __nv_bfloat16 g_alo[(size_t)MROWS * DIM];
__device__ __nv_bfloat16 g_wqh[(size_t)QKVDIM * KDIM];   // w_qkv^T [n][k]
__device__ __nv_bfloat16 g_wql[(size_t)QKVDIM * KDIM];
__device__ __nv_bfloat16 g_wph[(size_t)DIM * KDIM];      // w_proj^T [n][k]
__device__ __nv_bfloat16 g_wpl[(size_t)DIM * KDIM];

// ---- base-PTX helpers -----------------------------------------------------
__device__ __forceinline__ uint32_t smem_u32(const void* p) {
    uint32_t a;
    asm("{ .reg .u64 t; cvta.to.shared.u64 t, %1; cvt.u32.u64 %0, t; }"
        : "=r"(a) : "l"(p));
    return a;
}
#define CP_ASYNC16(s, g) asm volatile("cp.async.ca.shared.global [%0], [%1], 16;" :: "r"(s), "l"(g))
#define CP_COMMIT()      asm volatile("cp.async.commit_group;" ::: "memory")
#define CP_WAIT1()       asm volatile("cp.async.wait_group 1;" ::: "memory")
#define CP_WAIT0()       asm volatile("cp.async.wait_group 0;" ::: "memory")

__device__ __forceinline__ void ldsm_x4(uint32_t* r, uint32_t a) {
    asm volatile("ldmatrix.sync.aligned.m8n8.x4.shared.b16 {%0,%1,%2,%3}, [%4];"
                 : "=r"(r[0]), "=r"(r[1]), "=r"(r[2]), "=r"(r[3]) : "r"(a));
}
__device__ __forceinline__ void ldsm_x2(uint32_t* r, uint32_t a) {
    asm volatile("ldmatrix.sync.aligned.m8n8.x2.shared.b16 {%0,%1}, [%2];"
                 : "=r"(r[0]), "=r"(r[1]) : "r"(a));
}
__device__ __forceinline__ void mma16816(float* d, const uint32_t* a,
                                         const uint32_t* b) {
    asm volatile(
        "mma.sync.aligned.m16n8k16.row.col.f32.bf16.bf16.f32 "
        "{%0,%1,%2,%3}, {%4,%5,%6,%7}, {%8,%9}, {%0,%1,%2,%3};"
        : "+f"(d[0]), "+f"(d[1]), "+f"(d[2]), "+f"(d[3])
        : "r"(a[0]), "r"(a[1]), "r"(a[2]), "r"(a[3]), "r"(b[0]), "r"(b[1]));
}

// ---------------------------------------------------------------------------
// Convert kernels: fp32 -> bf16 hi + bf16 lo (residual)
// ---------------------------------------------------------------------------
__global__ void conv_split4(const float* __restrict__ x,
                            __nv_bfloat16* __restrict__ hi,
                            __nv_bfloat16* __restrict__ lo, long n4)
{
    long i = (long)blockIdx.x * blockDim.x + threadIdx.x;
    if (i >= n4) return;
    float4 v = ((const float4*)x)[i];
    __nv_bfloat16 h0 = __float2bfloat16(v.x), h1 = __float2bfloat16(v.y);
    __nv_bfloat16 h2 = __float2bfloat16(v.z), h3 = __float2bfloat16(v.w);
    __nv_bfloat16 hv[4] = {h0, h1, h2, h3};
    __nv_bfloat16 lv[4] = {
        __float2bfloat16(v.x - __bfloat162float(h0)),
        __float2bfloat16(v.y - __bfloat162float(h1)),
        __float2bfloat16(v.z - __bfloat162float(h2)),
        __float2bfloat16(v.w - __bfloat162float(h3))};
    ((uint2*)hi)[i] = *(uint2*)hv;
    ((uint2*)lo)[i] = *(uint2*)lv;
}

// w[k][n] (KxN row-major) -> hi/lo[n][k]  (transposed, K contiguous)
__global__ void conv_wT(const float* __restrict__ w,
                        __nv_bfloat16* __restrict__ hi,
                        __nv_bfloat16* __restrict__ lo, int K, int N)
{
    int i = blockIdx.x * blockDim.x + threadIdx.x;
    if (i >= K * N) return;
    int k = i / N, n = i % N;
    float v = w[i];
    __nv_bfloat16 h = __float2bfloat16(v);
    hi[(size_t)n * K + k] = h;
    lo[(size_t)n * K + k] = __float2bfloat16(v - __bfloat162float(h));
}

// ---------------------------------------------------------------------------
// mma.sync GEMM: C[M,Nld] = Ahi@Bhi^T + Ahi@Blo^T + Alo@Bhi^T + bias
//   A: [M][256] bf16 row-major; B: [Nld][256] bf16 (pre-transposed, K-major)
//   CTA 128x128, 512 thr (16 warps 4x4, warp tile 32x32), BK=32,
//   2-stage cp.async pipeline, 80B-padded smem rows (conflict-free ldmatrix).
// ---------------------------------------------------------------------------
#define BKI    32
#define RSTR   80                   // smem row stride bytes (64B data + 16 pad)
#define TBYTES (128 * RSTR)         // 10240 per tensor
#define STAGE  (4 * TBYTES)         // Ah, Al, Bh, Bl
#define GSMEM  (2 * STAGE)          // 81920

struct GParms {
    const char *pAh, *pAl, *pBh, *pBl;
};

__device__ __forceinline__ void stage_issue(uint32_t sbase, const GParms& g,
                                            int tid, int kt)
{
    const int  row = tid >> 2;
    const int  off = (tid & 3) * 16;
    const long go  = (long)row * (KDIM * 2) + (long)kt * (BKI * 2) + off;
    const uint32_t so = sbase + row * RSTR + off;
    CP_ASYNC16(so,              g.pAh + go);
    CP_ASYNC16(so + TBYTES,     g.pAl + go);
    CP_ASYNC16(so + 2 * TBYTES, g.pBh + go);
    CP_ASYNC16(so + 3 * TBYTES, g.pBl + go);
}

__global__ __launch_bounds__(512, 1)
void gemm_bf16x3(const __nv_bfloat16* __restrict__ Ahi,
                 const __nv_bfloat16* __restrict__ Alo,
                 const __nv_bfloat16* __restrict__ Bhi,
                 const __nv_bfloat16* __restrict__ Blo,
                 const float* __restrict__ bias,
                 float* __restrict__ C, int Nld)
{
    extern __shared__ char smem[];
    const uint32_t sb = smem_u32(smem);
    const int tid  = threadIdx.x;
    const int wid  = tid >> 5;
    const int lane = tid & 31;
    const int wm   = (wid >> 2) * 32;     // warp m-offset in tile
    const int wn   = (wid & 3) * 32;      // warp n-offset in tile
    const int  col0 = blockIdx.x * 128;
    const long row0 = (long)blockIdx.y * 128;

    GParms g;
    g.pAh = (const char*)Ahi + row0 * (KDIM * 2);
    g.pAl = (const char*)Alo + row0 * (KDIM * 2);
    g.pBh = (const char*)Bhi + (long)col0 * (KDIM * 2);
    g.pBl = (const char*)Blo + (long)col0 * (KDIM * 2);

    float acc[2][4][4];
    #pragma unroll
    for (int i = 0; i < 2; i++)
        #pragma unroll
        for (int j = 0; j < 4; j++)
            #pragma unroll
            for (int r = 0; r < 4; r++) acc[i][j][r] = 0.f;

    stage_issue(sb, g, tid, 0);             CP_COMMIT();
    stage_issue(sb + STAGE, g, tid, 1);     CP_COMMIT();

    // ldmatrix per-thread address components
    const int aRow  = lane & 15;            // A: row within 16-row atom
    const int aKoff = (lane >> 4) * 16;     // A: 8-col half -> *2 bytes
    const int bRow  = lane & 7;             // B: n-row within 8
    const int bKoff = ((lane >> 3) & 1) * 16;

    #pragma unroll 1
    for (int kt = 0; kt < KDIM / BKI; kt++) {
        if (kt < KDIM / BKI - 1) CP_WAIT1(); else CP_WAIT0();
        __syncthreads();

        const uint32_t sA = sb + (kt & 1) * STAGE;
        const uint32_t sB = sA + 2 * TBYTES;

        #pragma unroll
        for (int ks = 0; ks < 2; ks++) {
            uint32_t rah[2][4], ral[2][4], rbh[4][2], rbl[4][2];
            #pragma unroll
            for (int am = 0; am < 2; am++) {
                const uint32_t ad = sA + (wm + am * 16 + aRow) * RSTR
                                  + ks * 32 + aKoff;
                ldsm_x4(rah[am], ad);
                ldsm_x4(ral[am], ad + TBYTES);
            }
            #pragma unroll
            for (int an = 0; an < 4; an++) {
                const uint32_t bd = sB + (wn + an * 8 + bRow) * RSTR
                                  + ks * 32 + bKoff;
                ldsm_x2(rbh[an], bd);
                ldsm_x2(rbl[an], bd + TBYTES);
            }
            #pragma unroll
            for (int am = 0; am < 2; am++)
                #pragma unroll
                for (int an = 0; an < 4; an++) {
                    mma16816(acc[am][an], rah[am], rbh[an]);
                    mma16816(acc[am][an], rah[am], rbl[an]);
                    mma16816(acc[am][an], ral[am], rbh[an]);
                }
        }
        __syncthreads();
        if (kt + 2 < KDIM / BKI) {
            stage_issue(sb + (kt & 1) * STAGE, g, tid, kt + 2);
            CP_COMMIT();
        }
    }

    // epilogue: C frag thread map: rows g, g+8; cols 2*tg, 2*tg+1
    const int tg = lane & 3, gr = lane >> 2;
    float2 bv[4];
    #pragma unroll
    for (int an = 0; an < 4; an++)
        bv[an] = *(const float2*)(bias + col0 + wn + an * 8 + 2 * tg);

    #pragma unroll
    for (int am = 0; am < 2; am++) {
        const long r = row0 + wm + am * 16 + gr;
        float* c0 = C + r * Nld + col0 + wn;
        float* c1 = C + (r + 8) * Nld + col0 + wn;
        #pragma unroll
        for (int an = 0; an < 4; an++) {
            float2 o0 = {acc[am][an][0] + bv[an].x, acc[am][an][1] + bv[an].y};
            float2 o1 = {acc[am][an][2] + bv[an].x, acc[am][an][3] + bv[an].y};
            *(float2*)(c0 + an * 8 + 2 * tg) = o0;
            *(float2*)(c1 + an * 8 + 2 * tg) = o1;
        }
    }
}

// ---------------------------------------------------------------------------
// Fused attention (validated in Round 4's pass; epilogue emits bf16 hi/lo)
// ---------------------------------------------------------------------------
__global__ __launch_bounds__(128) void attn_kernel(
    const float* __restrict__ qkv, const float* __restrict__ bias_table,
    __nv_bfloat16* __restrict__ ohi, __nv_bfloat16* __restrict__ olo)
{
    const int h    = blockIdx.x;
    const int b    = blockIdx.y;
    const int t    = threadIdx.x;
    const int w    = t >> 5;
    const int lane = t & 31;

    __shared__ float sq[NTOK * 33];
    __shared__ float sk[64 * 33];
    __shared__ float sv[NTOK * 33];
    __shared__ float sbt[169];

    for (int idx = t; idx < (64 - NTOK) * 33; idx += 128) sk[NTOK * 33 + idx] = 0.f;
    for (int idx = t; idx < 169; idx += 128) sbt[idx] = bias_table[idx * HEADS + h];

    const float scale = 0.17677669529663687f;
    const float* base = qkv + (size_t)b * NTOK * QKVDIM + (size_t)h * HD;
    for (int idx = t; idx < NTOK * HD; idx += 128) {
        const int n = idx >> 5, d = idx & 31;
        const float* p = base + (size_t)n * QKVDIM + d;
        sq[n * 33 + d] = p[0] * scale;
        sk[n * 33 + d] = p[DIM];
        sv[n * 33 + d] = p[2 * DIM];
    }
    __syncthreads();

    float vreg[NTOK];
    #pragma unroll
    for (int j = 0; j < NTOK; j++) vreg[j] = sv[j * 33 + lane];

    const int  j0  = lane;
    const int  j1  = lane + 32;
    const bool vs1 = (j1 < NTOK);
    const int  hj0 = j0 / 7, wj0 = j0 % 7;
    const int  j1c = vs1 ? j1 : 0;
    const int  hj1 = j1c / 7, wj1 = j1c % 7;

    const size_t ob = (size_t)b * NTOK * DIM + (size_t)h * HD + lane;

    for (int i = w; i < NTOK; i += 4) {
        const int hi = i / 7, wi = i % 7;
        const float* qrow  = sq + i * 33;
        const float* krow0 = sk + j0 * 33;
        const float* krow1 = sk + j1 * 33;

        float a0 = 0.f, a1 = 0.f;
        #pragma unroll
        for (int d = 0; d < HD; d++) {
            const float qv = qrow[d];
            a0 += qv * krow0[d];
            a1 += qv * krow1[d];
        }
        a0 += sbt[(hi - hj0 + 6) * 13 + (wi - wj0 + 6)];
        a1 = vs1 ? (a1 + sbt[(hi - hj1 + 6) * 13 + (wi - wj1 + 6)]) : -3.0e38f;

        float m = fmaxf(a0, a1);
        #pragma unroll
        for (int o = 16; o > 0; o >>= 1)
            m = fmaxf(m, __shfl_xor_sync(0xffffffffu, m, o));
        float p0 = __expf(a0 - m);
        float p1 = vs1 ? __expf(a1 - m) : 0.f;
        float s = p0 + p1;
        #pragma unroll
        for (int o = 16; o > 0; o >>= 1)
            s += __shfl_xor_sync(0xffffffffu, s, o);
        const float r = 1.f / s;
        p0 *= r;
        p1 *= r;

        float o = 0.f;
        #pragma unroll
        for (int j = 0; j < 32; j++)
            o += __shfl_sync(0xffffffffu, p0, j) * vreg[j];
        #pragma unroll
        for (int j = 0; j < 17; j++)
            o += __shfl_sync(0xffffffffu, p1, j) * vreg[32 + j];

        const __nv_bfloat16 hb = __float2bfloat16(o);
        ohi[ob + (size_t)i * DIM] = hb;
        olo[ob + (size_t)i * DIM] = __float2bfloat16(o - __bfloat162float(hb));
    }
}

// ---------------------------------------------------------------------------
extern "C" void kernel_launch(void* const* d_in, const int* in_sizes, int n_in,
                              void* d_out, int out_size)
{
    const float* x          = (const float*)d_in[0];
    const float* w_qkv      = (const float*)d_in[1];
    const float* b_qkv      = (const float*)d_in[2];
    const float* w_proj     = (const float*)d_in[3];
    const float* b_proj     = (const float*)d_in[4];
    const float* bias_table = (const float*)d_in[5];
    float* out = (float*)d_out;

    float* qkvp = nullptr;
    __nv_bfloat16 *xhi, *xlo, *ahi, *alo, *wqh, *wql, *wph, *wpl;
    cudaGetSymbolAddress((void**)&qkvp, g_qkv);
    cudaGetSymbolAddress((void**)&xhi, g_xhi);
    cudaGetSymbolAddress((void**)&xlo, g_xlo);
    cudaGetSymbolAddress((void**)&ahi, g_ahi);
    cudaGetSymbolAddress((void**)&alo, g_alo);
    cudaGetSymbolAddress((void**)&wqh, g_wqh);
    cudaGetSymbolAddress((void**)&wql, g_wql);
    cudaGetSymbolAddress((void**)&wph, g_wph);
    cudaGetSymbolAddress((void**)&wpl, g_wpl);

    cudaFuncSetAttribute(gemm_bf16x3,
                         cudaFuncAttributeMaxDynamicSharedMemorySize, GSMEM);

    // split x -> bf16 hi/lo
    {
        long n4 = (long)MROWS * DIM / 4;
        conv_split4<<<(unsigned)((n4 + 255) / 256), 256>>>(x, xhi, xlo, n4);
    }
    // weights -> transposed bf16 hi/lo
    conv_wT<<<(KDIM * QKVDIM + 255) / 256, 256>>>(w_qkv, wqh, wql, KDIM, QKVDIM);
    conv_wT<<<(KDIM * DIM + 255) / 256, 256>>>(w_proj, wph, wpl, KDIM, DIM);

    // K1: qkv = x @ w_qkv + b_qkv
    {
        dim3 grid(QKVDIM / 128, MROWS / 128);
        gemm_bf16x3<<<grid, 512, GSMEM>>>(xhi, xlo, wqh, wql, b_qkv, qkvp, QKVDIM);
    }
    // K2: fused attention -> bf16 hi/lo
    {
        dim3 grid(HEADS, BATCH);
        attn_kernel<<<grid, 128>>>(qkvp, bias_table, ahi, alo);
    }
    // K3: out = att @ w_proj + b_proj
    {
        dim3 grid(DIM / 128, MROWS / 128);
        gemm_bf16x3<<<grid, 512, GSMEM>>>(ahi, alo, wph, wpl, b_proj, out, DIM);
    }
}

// round 7
// speedup vs baseline: 1.7457x; 1.2046x over previous
#include <cuda_runtime.h>
#include <cuda_bf16.h>
#include <cstdint>
#include <cstddef>

// ---------------------------------------------------------------------------
// WindowAttention, base-PTX tensor-core path (compute_103-safe).
// K1/K3: D = Ahi@Bhi^T + Ahi@Blo^T + Alo@Bhi^T  (3-term bf16 split, fp32 acc)
// R7: term-major MMA (indep chains), 3-stage cp.async (1 sync/iter),
//     paired-x4 B ldmatrix, attention K-register hoist + float4 staging.
// ---------------------------------------------------------------------------

#define BATCH   4096
#define NTOK    49
#define HEADS   8
#define DIM     256
#define HD      32
#define QKVDIM  768
#define MROWS   (BATCH * NTOK)   // 200704 = 1568 * 128
#define KDIM    256

// ---- scratch (static __device__: allocation-guard-safe) -------------------
__device__ float         g_qkv[(size_t)MROWS * QKVDIM];
__device__ __nv_bfloat16 g_xhi[(size_t)MROWS * DIM];
__device__ __nv_bfloat16 g_xlo[(size_t)MROWS * DIM];
__device__ __nv_bfloat16 g_ahi[(size_t)MROWS * DIM];
__device__ __nv_bfloat16 g_alo[(size_t)MROWS * DIM];
__device__ __nv_bfloat16 g_wqh[(size_t)QKVDIM * KDIM];   // w_qkv^T [n][k]
__device__ __nv_bfloat16 g_wql[(size_t)QKVDIM * KDIM];
__device__ __nv_bfloat16 g_wph[(size_t)DIM * KDIM];      // w_proj^T [n][k]
__device__ __nv_bfloat16 g_wpl[(size_t)DIM * KDIM];

// ---- base-PTX helpers -----------------------------------------------------
__device__ __forceinline__ uint32_t smem_u32(const void* p) {
    uint32_t a;
    asm("{ .reg .u64 t; cvta.to.shared.u64 t, %1; cvt.u32.u64 %0, t; }"
        : "=r"(a) : "l"(p));
    return a;
}
#define CP_ASYNC16(s, g) asm volatile("cp.async.ca.shared.global [%0], [%1], 16;" :: "r"(s), "l"(g))
#define CP_COMMIT()      asm volatile("cp.async.commit_group;" ::: "memory")
#define CP_WAIT1()       asm volatile("cp.async.wait_group 1;" ::: "memory")
#define CP_WAIT0()       asm volatile("cp.async.wait_group 0;" ::: "memory")

__device__ __forceinline__ void ldsm_x4(uint32_t* r, uint32_t a) {
    asm volatile("ldmatrix.sync.aligned.m8n8.x4.shared.b16 {%0,%1,%2,%3}, [%4];"
                 : "=r"(r[0]), "=r"(r[1]), "=r"(r[2]), "=r"(r[3]) : "r"(a));
}
__device__ __forceinline__ void mma16816(float* d, const uint32_t* a,
                                         const uint32_t* b) {
    asm volatile(
        "mma.sync.aligned.m16n8k16.row.col.f32.bf16.bf16.f32 "
        "{%0,%1,%2,%3}, {%4,%5,%6,%7}, {%8,%9}, {%0,%1,%2,%3};"
        : "+f"(d[0]), "+f"(d[1]), "+f"(d[2]), "+f"(d[3])
        : "r"(a[0]), "r"(a[1]), "r"(a[2]), "r"(a[3]), "r"(b[0]), "r"(b[1]));
}

// ---------------------------------------------------------------------------
// Convert kernels: fp32 -> bf16 hi + bf16 lo (residual)
// ---------------------------------------------------------------------------
__global__ void conv_split4(const float* __restrict__ x,
                            __nv_bfloat16* __restrict__ hi,
                            __nv_bfloat16* __restrict__ lo, long n4)
{
    long i = (long)blockIdx.x * blockDim.x + threadIdx.x;
    if (i >= n4) return;
    float4 v = ((const float4*)x)[i];
    __nv_bfloat16 h0 = __float2bfloat16(v.x), h1 = __float2bfloat16(v.y);
    __nv_bfloat16 h2 = __float2bfloat16(v.z), h3 = __float2bfloat16(v.w);
    __nv_bfloat16 hv[4] = {h0, h1, h2, h3};
    __nv_bfloat16 lv[4] = {
        __float2bfloat16(v.x - __bfloat162float(h0)),
        __float2bfloat16(v.y - __bfloat162float(h1)),
        __float2bfloat16(v.z - __bfloat162float(h2)),
        __float2bfloat16(v.w - __bfloat162float(h3))};
    ((uint2*)hi)[i] = *(uint2*)hv;
    ((uint2*)lo)[i] = *(uint2*)lv;
}

// w[k][n] (KxN row-major) -> hi/lo[n][k]  (transposed, K contiguous)
__global__ void conv_wT(const float* __restrict__ w,
                        __nv_bfloat16* __restrict__ hi,
                        __nv_bfloat16* __restrict__ lo, int K, int N)
{
    int i = blockIdx.x * blockDim.x + threadIdx.x;
    if (i >= K * N) return;
    int k = i / N, n = i % N;
    float v = w[i];
    __nv_bfloat16 h = __float2bfloat16(v);
    hi[(size_t)n * K + k] = h;
    lo[(size_t)n * K + k] = __float2bfloat16(v - __bfloat162float(h));
}

// ---------------------------------------------------------------------------
// mma.sync GEMM: C[M,Nld] = Ahi@Bhi^T + Ahi@Blo^T + Alo@Bhi^T + bias
//   CTA 128x128, 512 thr (16 warps 4x4, warp 32x32), BK=32, 3-stage cp.async.
// ---------------------------------------------------------------------------
#define BKI    32
#define RSTR   80                   // smem row stride bytes (64B data + 16 pad)
#define TBYTES (128 * RSTR)         // 10240 per tensor
#define STG_B  (4 * TBYTES)         // Ah, Al, Bh, Bl = 40960
#define NSTG   3
#define GSMEM  (NSTG * STG_B)       // 122880

struct GParms { const char *pAh, *pAl, *pBh, *pBl; };

__device__ __forceinline__ void stage_issue(uint32_t sbase, const GParms& g,
                                            int tid, int kt)
{
    const int  row = tid >> 2;
    const int  off = (tid & 3) * 16;
    const long go  = (long)row * (KDIM * 2) + (long)kt * (BKI * 2) + off;
    const uint32_t so = sbase + row * RSTR + off;
    CP_ASYNC16(so,              g.pAh + go);
    CP_ASYNC16(so + TBYTES,     g.pAl + go);
    CP_ASYNC16(so + 2 * TBYTES, g.pBh + go);
    CP_ASYNC16(so + 3 * TBYTES, g.pBl + go);
}

__global__ __launch_bounds__(512, 1)
void gemm_bf16x3(const __nv_bfloat16* __restrict__ Ahi,
                 const __nv_bfloat16* __restrict__ Alo,
                 const __nv_bfloat16* __restrict__ Bhi,
                 const __nv_bfloat16* __restrict__ Blo,
                 const float* __restrict__ bias,
                 float* __restrict__ C, int Nld)
{
    extern __shared__ char smem[];
    const uint32_t sb = smem_u32(smem);
    const int tid  = threadIdx.x;
    const int wid  = tid >> 5;
    const int lane = tid & 31;
    const int wm   = (wid >> 2) * 32;
    const int wn   = (wid & 3) * 32;
    const int  col0 = blockIdx.x * 128;
    const long row0 = (long)blockIdx.y * 128;

    GParms g;
    g.pAh = (const char*)Ahi + row0 * (KDIM * 2);
    g.pAl = (const char*)Alo + row0 * (KDIM * 2);
    g.pBh = (const char*)Bhi + (long)col0 * (KDIM * 2);
    g.pBl = (const char*)Blo + (long)col0 * (KDIM * 2);

    float acc[2][4][4];
    #pragma unroll
    for (int i = 0; i < 2; i++)
        #pragma unroll
        for (int j = 0; j < 4; j++)
            #pragma unroll
            for (int r = 0; r < 4; r++) acc[i][j][r] = 0.f;

    stage_issue(sb,         g, tid, 0);  CP_COMMIT();
    stage_issue(sb + STG_B, g, tid, 1);  CP_COMMIT();

    // ldmatrix per-thread address components
    const int aRow  = lane & 15;              // A: row within 16-row atom
    const int aKoff = (lane >> 4) * 16;       // A: k-half byte offset
    const int bMat  = lane >> 3;              // B paired-x4: matrix idx 0..3
    const int bRow  = lane & 7;
    const int bNa   = bMat >> 1;              // +0/+1 n-atom within pair
    const int bKoff = (bMat & 1) * 16;        // k-half byte offset

    const int NK = KDIM / BKI;                // 8
    #pragma unroll 1
    for (int kt = 0; kt < NK; kt++) {
        if (kt == NK - 1) CP_WAIT0(); else CP_WAIT1();
        __syncthreads();
        if (kt + 2 < NK) {
            stage_issue(sb + ((kt + 2) % NSTG) * STG_B, g, tid, kt + 2);
            CP_COMMIT();
        }

        const uint32_t sA = sb + (kt % NSTG) * STG_B;
        const uint32_t sB = sA + 2 * TBYTES;

        #pragma unroll
        for (int ks = 0; ks < 2; ks++) {
            uint32_t rah[2][4], ral[2][4], rbh[4][2], rbl[4][2];
            #pragma unroll
            for (int am = 0; am < 2; am++) {
                const uint32_t ad = sA + (wm + am * 16 + aRow) * RSTR
                                  + ks * 32 + aKoff;
                ldsm_x4(rah[am], ad);
                ldsm_x4(ral[am], ad + TBYTES);
            }
            #pragma unroll
            for (int ap = 0; ap < 2; ap++) {   // n-atom pairs {0,1},{2,3}
                uint32_t t4[4];
                const uint32_t bd = sB + (wn + (ap * 2 + bNa) * 8 + bRow) * RSTR
                                  + ks * 32 + bKoff;
                ldsm_x4(t4, bd);
                rbh[ap * 2][0] = t4[0]; rbh[ap * 2][1] = t4[1];
                rbh[ap * 2 + 1][0] = t4[2]; rbh[ap * 2 + 1][1] = t4[3];
                ldsm_x4(t4, bd + TBYTES);
                rbl[ap * 2][0] = t4[0]; rbl[ap * 2][1] = t4[1];
                rbl[ap * 2 + 1][0] = t4[2]; rbl[ap * 2 + 1][1] = t4[3];
            }
            // term-major: 8 independent MMAs between accumulator reuses
            #pragma unroll
            for (int am = 0; am < 2; am++)
                #pragma unroll
                for (int an = 0; an < 4; an++)
                    mma16816(acc[am][an], rah[am], rbh[an]);
            #pragma unroll
            for (int am = 0; am < 2; am++)
                #pragma unroll
                for (int an = 0; an < 4; an++)
                    mma16816(acc[am][an], rah[am], rbl[an]);
            #pragma unroll
            for (int am = 0; am < 2; am++)
                #pragma unroll
                for (int an = 0; an < 4; an++)
                    mma16816(acc[am][an], ral[am], rbh[an]);
        }
    }

    // epilogue: C frag map: rows gr, gr+8; cols 2*tg, 2*tg+1
    const int tg = lane & 3, gr = lane >> 2;
    float2 bv[4];
    #pragma unroll
    for (int an = 0; an < 4; an++)
        bv[an] = *(const float2*)(bias + col0 + wn + an * 8 + 2 * tg);

    #pragma unroll
    for (int am = 0; am < 2; am++) {
        const long r = row0 + wm + am * 16 + gr;
        float* c0 = C + r * Nld + col0 + wn;
        float* c1 = C + (r + 8) * Nld + col0 + wn;
        #pragma unroll
        for (int an = 0; an < 4; an++) {
            float2 o0 = {acc[am][an][0] + bv[an].x, acc[am][an][1] + bv[an].y};
            float2 o1 = {acc[am][an][2] + bv[an].x, acc[am][an][3] + bv[an].y};
            *(float2*)(c0 + an * 8 + 2 * tg) = o0;
            *(float2*)(c1 + an * 8 + 2 * tg) = o1;
        }
    }
}

// ---------------------------------------------------------------------------
// Fused attention. R7: K rows hoisted to registers (loop-invariant per lane),
// float4 staging with 36-float row stride; emits bf16 hi/lo for K3.
// ---------------------------------------------------------------------------
__global__ __launch_bounds__(128) void attn_kernel(
    const float* __restrict__ qkv, const float* __restrict__ bias_table,
    __nv_bfloat16* __restrict__ ohi, __nv_bfloat16* __restrict__ olo)
{
    const int h    = blockIdx.x;
    const int b    = blockIdx.y;
    const int t    = threadIdx.x;
    const int w    = t >> 5;
    const int lane = t & 31;

    __shared__ float sq[NTOK * 36];
    __shared__ float sk[NTOK * 36];
    __shared__ float sv[NTOK * 36];
    __shared__ float sbt[169];

    for (int idx = t; idx < 169; idx += 128) sbt[idx] = bias_table[idx * HEADS + h];

    const float scale = 0.17677669529663687f;  // 1/sqrt(32)
    const float* base = qkv + (size_t)b * NTOK * QKVDIM + (size_t)h * HD;
    // stage q (scaled), k, v as float4: 49 rows x 8 float4 each
    for (int idx = t; idx < NTOK * 8; idx += 128) {
        const int n = idx >> 3, d4 = idx & 7;
        const float4* p = (const float4*)(base + (size_t)n * QKVDIM) + d4;
        float4 qv = p[0];
        qv.x *= scale; qv.y *= scale; qv.z *= scale; qv.w *= scale;
        *(float4*)(sq + n * 36 + 4 * d4) = qv;
        *(float4*)(sk + n * 36 + 4 * d4) = p[DIM / 4];      // k
        *(float4*)(sv + n * 36 + 4 * d4) = p[2 * (DIM / 4)];// v
    }
    __syncthreads();

    // per-lane register caches (loop-invariant across rows)
    float vreg[NTOK];
    #pragma unroll
    for (int j = 0; j < NTOK; j++) vreg[j] = sv[j * 36 + lane];

    const int  j0  = lane;
    const bool vs1 = (lane + 32 < NTOK);
    const int  j1c = vs1 ? lane + 32 : 0;     // clamped; invalid lanes discard
    float kr0[HD], kr1[HD];
    #pragma unroll
    for (int d = 0; d < HD; d++) kr0[d] = sk[j0 * 36 + d];
    #pragma unroll
    for (int d = 0; d < HD; d++) kr1[d] = sk[j1c * 36 + d];

    const int hj0 = j0 / 7,  wj0 = j0 % 7;
    const int hj1 = j1c / 7, wj1 = j1c % 7;

    const size_t ob = (size_t)b * NTOK * DIM + (size_t)h * HD + lane;

    for (int i = w; i < NTOK; i += 4) {
        const int hi = i / 7, wi = i % 7;
        const float* qrow = sq + i * 36;

        float a0 = 0.f, a1 = 0.f;
        #pragma unroll
        for (int d = 0; d < HD; d++) {
            const float qv = qrow[d];       // broadcast LDS
            a0 += qv * kr0[d];
            a1 += qv * kr1[d];
        }
        a0 += sbt[(hi - hj0 + 6) * 13 + (wi - wj0 + 6)];
        a1 = vs1 ? (a1 + sbt[(hi - hj1 + 6) * 13 + (wi - wj1 + 6)]) : -3.0e38f;

        float m = fmaxf(a0, a1);
        #pragma unroll
        for (int o = 16; o > 0; o >>= 1)
            m = fmaxf(m, __shfl_xor_sync(0xffffffffu, m, o));
        float p0 = __expf(a0 - m);
        float p1 = vs1 ? __expf(a1 - m) : 0.f;
        float s = p0 + p1;
        #pragma unroll
        for (int o = 16; o > 0; o >>= 1)
            s += __shfl_xor_sync(0xffffffffu, s, o);
        const float r = 1.f / s;
        p0 *= r;
        p1 *= r;

        float o = 0.f;
        #pragma unroll
        for (int j = 0; j < 32; j++)
            o += __shfl_sync(0xffffffffu, p0, j) * vreg[j];
        #pragma unroll
        for (int j = 0; j < 17; j++)
            o += __shfl_sync(0xffffffffu, p1, j) * vreg[32 + j];

        const __nv_bfloat16 hb = __float2bfloat16(o);
        ohi[ob + (size_t)i * DIM] = hb;
        olo[ob + (size_t)i * DIM] = __float2bfloat16(o - __bfloat162float(hb));
    }
}

// ---------------------------------------------------------------------------
extern "C" void kernel_launch(void* const* d_in, const int* in_sizes, int n_in,
                              void* d_out, int out_size)
{
    const float* x          = (const float*)d_in[0];
    const float* w_qkv      = (const float*)d_in[1];
    const float* b_qkv      = (const float*)d_in[2];
    const float* w_proj     = (const float*)d_in[3];
    const float* b_proj     = (const float*)d_in[4];
    const float* bias_table = (const float*)d_in[5];
    float* out = (float*)d_out;

    float* qkvp = nullptr;
    __nv_bfloat16 *xhi, *xlo, *ahi, *alo, *wqh, *wql, *wph, *wpl;
    cudaGetSymbolAddress((void**)&qkvp, g_qkv);
    cudaGetSymbolAddress((void**)&xhi, g_xhi);
    cudaGetSymbolAddress((void**)&xlo, g_xlo);
    cudaGetSymbolAddress((void**)&ahi, g_ahi);
    cudaGetSymbolAddress((void**)&alo, g_alo);
    cudaGetSymbolAddress((void**)&wqh, g_wqh);
    cudaGetSymbolAddress((void**)&wql, g_wql);
    cudaGetSymbolAddress((void**)&wph, g_wph);
    cudaGetSymbolAddress((void**)&wpl, g_wpl);

    cudaFuncSetAttribute(gemm_bf16x3,
                         cudaFuncAttributeMaxDynamicSharedMemorySize, GSMEM);

    // split x -> bf16 hi/lo
    {
        long n4 = (long)MROWS * DIM / 4;
        conv_split4<<<(unsigned)((n4 + 255) / 256), 256>>>(x, xhi, xlo, n4);
    }
    // weights -> transposed bf16 hi/lo
    conv_wT<<<(KDIM * QKVDIM + 255) / 256, 256>>>(w_qkv, wqh, wql, KDIM, QKVDIM);
    conv_wT<<<(KDIM * DIM + 255) / 256, 256>>>(w_proj, wph, wpl, KDIM, DIM);

    // K1: qkv = x @ w_qkv + b_qkv
    {
        dim3 grid(QKVDIM / 128, MROWS / 128);
        gemm_bf16x3<<<grid, 512, GSMEM>>>(xhi, xlo, wqh, wql, b_qkv, qkvp, QKVDIM);
    }
    // K2: fused attention -> bf16 hi/lo
    {
        dim3 grid(HEADS, BATCH);
        attn_kernel<<<grid, 128>>>(qkvp, bias_table, ahi, alo);
    }
    // K3: out = att @ w_proj + b_proj
    {
        dim3 grid(DIM / 128, MROWS / 128);
        gemm_bf16x3<<<grid, 512, GSMEM>>>(ahi, alo, wph, wpl, b_proj, out, DIM);
    }
}